// round 8
// baseline (speedup 1.0000x reference)
#include <cuda_runtime.h>

// MPSLayer, fused single kernel.
//   out[b,o]  = s[b]*v[o] + bias[o]
//   s[b]      = prod_n x[b,n]          (local per epilogue block)
//   u         = ones^T @ core_0 @ ... @ core_255
//   Psum[r,o] = sum_l proj[r,l,o]
//   v[o]      = sum_r u[r]*Psum[r,o]
// Tree: 64 blocks ∏4 cores -> D ; blocks 0..15 ∏4 D -> E (stored TRANSPOSED);
//       block 0: 16-step vector chain via cp.async ring (per-lane column
//       slices, XOR-swizzled 16B chunks) -> u -> v.
// Grid 128 x 256 (blocks 64..127 compute Psum); all co-resident.

#define DD      32
#define N_IN    256
#define BATCH   1024
#define OUT_DIM 512

__device__ __align__(16) float g_D[64 * 1024];
__device__ __align__(16) float g_E[16 * 1024];   // column-major (E^T)
__device__ __align__(16) float g_Psum[DD * OUT_DIM];
__device__ __align__(16) float g_v[OUT_DIM];

__device__ int g_cnt_D4[16];     // 4 producers, 1 poller each
__device__ int g_cnt_E;          // 15 producers, 1 poller (block 0)
__device__ int g_cnt_P;          // 64 producers, 1 poller (block 0)
__device__ int g_flag_v_p[128];  // private: 1 writer thread, 1 poller each

// ---- sync primitives --------------------------------------------------------
__device__ __forceinline__ int ld_acq(const int* p) {
    int v;
    asm volatile("ld.acquire.gpu.global.b32 %0, [%1];" : "=r"(v) : "l"(p) : "memory");
    return v;
}
__device__ __forceinline__ int ld_rlx(const int* p) {
    int v;
    asm volatile("ld.relaxed.gpu.global.b32 %0, [%1];" : "=r"(v) : "l"(p) : "memory");
    return v;
}
__device__ __forceinline__ void red_rel_add(int* p, int v) {
    asm volatile("red.release.gpu.global.add.s32 [%0], %1;" :: "l"(p), "r"(v) : "memory");
}
__device__ __forceinline__ void st_relaxed(int* p, int v) {
    asm volatile("st.relaxed.gpu.global.b32 [%0], %1;" :: "l"(p), "r"(v) : "memory");
}
__device__ __forceinline__ void spin_ge(int* cnt, int target) {
    if (threadIdx.x == 0) {
        while (ld_rlx(cnt) < target) { }
        (void)ld_acq(cnt);
    }
    __syncthreads();
}

// ---- cp.async ---------------------------------------------------------------
__device__ __forceinline__ void cpa16(unsigned dst, const float* src) {
    asm volatile("cp.async.ca.shared.global [%0], [%1], 16;" :: "r"(dst), "l"(src));
}
#define CP_COMMIT() asm volatile("cp.async.commit_group;" ::: "memory")
#define CP_WAIT(n)  asm volatile("cp.async.wait_group %0;" :: "n"(n) : "memory")

// ---------------------------------------------------------------------------
// Register-resident 32x32 step: thread owns P[l][4q..4q+3] (l=tid>>3, q=tid&7);
// returns P @ B(smem row-major). Row values gathered by shfl within the 8-lane
// row group.
// ---------------------------------------------------------------------------
__device__ __forceinline__ float4 mm_step_reg(float4 p, const float4* __restrict__ B4,
                                              int lane, int q) {
    float4 acc = make_float4(0.f, 0.f, 0.f, 0.f);
    int grp = lane & 24;
    #pragma unroll
    for (int j = 0; j < 8; ++j) {
        float a; float4 b;
        a = __shfl_sync(0xffffffffu, p.x, grp + j);
        b = B4[(4 * j + 0) * 8 + q];
        acc.x = fmaf(a, b.x, acc.x); acc.y = fmaf(a, b.y, acc.y);
        acc.z = fmaf(a, b.z, acc.z); acc.w = fmaf(a, b.w, acc.w);
        a = __shfl_sync(0xffffffffu, p.y, grp + j);
        b = B4[(4 * j + 1) * 8 + q];
        acc.x = fmaf(a, b.x, acc.x); acc.y = fmaf(a, b.y, acc.y);
        acc.z = fmaf(a, b.z, acc.z); acc.w = fmaf(a, b.w, acc.w);
        a = __shfl_sync(0xffffffffu, p.z, grp + j);
        b = B4[(4 * j + 2) * 8 + q];
        acc.x = fmaf(a, b.x, acc.x); acc.y = fmaf(a, b.y, acc.y);
        acc.z = fmaf(a, b.z, acc.z); acc.w = fmaf(a, b.w, acc.w);
        a = __shfl_sync(0xffffffffu, p.w, grp + j);
        b = B4[(4 * j + 3) * 8 + q];
        acc.x = fmaf(a, b.x, acc.x); acc.y = fmaf(a, b.y, acc.y);
        acc.z = fmaf(a, b.z, acc.z); acc.w = fmaf(a, b.w, acc.w);
    }
    return acc;
}

// Product of 4 consecutive 32x32 matrices (global, row-major), result in regs.
__device__ __forceinline__ float4 mm_chain4_reg(const float4* __restrict__ src4,
                                                float4* sB0, float4* sB1) {
    int tid = threadIdx.x, lane = tid & 31, q = tid & 7;
    float4 p  = src4[tid];
    float4 b1 = src4[256 + tid];
    float4 b2 = src4[512 + tid];
    float4 b3 = src4[768 + tid];
    sB0[tid] = b1; __syncthreads();
    p = mm_step_reg(p, sB0, lane, q);
    sB1[tid] = b2; __syncthreads();
    p = mm_step_reg(p, sB1, lane, q);
    sB0[tid] = b3; __syncthreads();
    p = mm_step_reg(p, sB0, lane, q);
    return p;
}

// ---------------------------------------------------------------------------
// Chain step with transposed stage: lane owns column `lane` (128B contiguous,
// 16B chunks XOR-swizzled by lane&7). u distributed via smem broadcast.
// ---------------------------------------------------------------------------
__device__ __forceinline__ float chain_step_t(float u, const float* __restrict__ stage,
                                              float* __restrict__ sUbuf, int lane) {
    sUbuf[lane] = u;
    __syncwarp();
    const float4* u4 = reinterpret_cast<const float4*>(sUbuf);
    const float4* c4 = reinterpret_cast<const float4*>(stage + lane * 32);
    int sw = lane & 7;
    float4 acc = make_float4(0.f, 0.f, 0.f, 0.f);
    #pragma unroll
    for (int k = 0; k < 8; ++k) {
        float4 uu = u4[k];
        float4 cc = c4[k ^ sw];      // chunk k lives at position k^sw
        acc.x = fmaf(uu.x, cc.x, acc.x);
        acc.y = fmaf(uu.y, cc.y, acc.y);
        acc.z = fmaf(uu.z, cc.z, acc.z);
        acc.w = fmaf(uu.w, cc.w, acc.w);
    }
    __syncwarp();                    // reads done before next step's STS
    return (acc.x + acc.y) + (acc.z + acc.w);
}

// ---------------------------------------------------------------------------
__global__ void __launch_bounds__(256) fused_mps(
    const float* __restrict__ x, const float* __restrict__ cores,
    const float* __restrict__ proj, const float* __restrict__ bias,
    float* __restrict__ out) {

    __shared__ __align__(16) float sm[4 * 1024];   // 4 ring stages x 4KB
    __shared__ __align__(16) float sU[DD];
    __shared__ float sS[8];
    int tid = threadIdx.x;
    int blk = blockIdx.x;
    int lane = tid & 31;
    int w = tid >> 5;
    int l = tid >> 3, q = tid & 7;

    // ---- entry prefetches ----------------------------------------------------
    int o4 = tid & 127;
    float4 bi = reinterpret_cast<const float4*>(bias)[o4];
    const float4* x4 = reinterpret_cast<const float4*>(x);
    int xrow = blk * 8 + w;
    float4 xa = x4[xrow * 64 + lane];
    float4 xb = x4[xrow * 64 + 32 + lane];

    float4* stg0 = reinterpret_cast<float4*>(sm);
    float4* stg1 = reinterpret_cast<float4*>(sm + 1024);
    unsigned smb = (unsigned)__cvta_generic_to_shared(sm);

    if (blk < 64) {
        // ---- level 1: D[blk] = product of 4 cores (row-major)
        float4 p = mm_chain4_reg(
            reinterpret_cast<const float4*>(cores) + (size_t)blk * 1024, stg0, stg1);
        reinterpret_cast<float4*>(g_D)[blk * 256 + tid] = p;
        __syncthreads();
        if (tid == 0) red_rel_add(&g_cnt_D4[blk >> 2], 1);

        if (blk < 16) {
            // ---- level 2: E[blk] = D[4blk] @ .. @ D[4blk+3]
            spin_ge(&g_cnt_D4[blk], 4);
            if (tid == 0) st_relaxed(&g_cnt_D4[blk], 0);
            float4 e = mm_chain4_reg(
                reinterpret_cast<const float4*>(g_D) + (size_t)blk * 1024, stg0, stg1);
            // thread's values: E[row=l][col=4q+j], j=0..3
            if (blk > 0) {
                // publish TRANSPOSED: g_E[blk*1024 + col*32 + row]
                float* dstE = g_E + blk * 1024 + l;
                dstE[(4 * q + 0) * 32] = e.x;
                dstE[(4 * q + 1) * 32] = e.y;
                dstE[(4 * q + 2) * 32] = e.z;
                dstE[(4 * q + 3) * 32] = e.w;
                __syncthreads();
                if (tid == 0) red_rel_add(&g_cnt_E, 1);
            } else {
                // E0 straight into ring stage 0, column-major + chunk swizzle:
                // float idx = col*32 + ((k ^ (col&7))*4) + (row&3), k = row>>2
                __syncthreads();             // mm reads of stage 0 complete
                int k = l >> 2, rlo = l & 3;
                float ev[4] = { e.x, e.y, e.z, e.w };
                #pragma unroll
                for (int j = 0; j < 4; ++j) {
                    int c = 4 * q + j;
                    sm[c * 32 + ((k ^ (c & 7)) << 2) + rlo] = ev[j];
                }
            }
        }
        if (blk == 0) {
            // Psum ready early: sync + prefetch its columns into registers
            spin_ge(&g_cnt_P, 64);
            if (tid == 0) st_relaxed(&g_cnt_P, 0);
            float pc0[DD], pc1[DD];
            #pragma unroll
            for (int r = 0; r < DD; ++r) pc0[r] = g_Psum[r * OUT_DIM + tid];
            #pragma unroll
            for (int r = 0; r < DD; ++r) pc1[r] = g_Psum[r * OUT_DIM + tid + 256];

            spin_ge(&g_cnt_E, 15);
            if (tid == 0) st_relaxed(&g_cnt_E, 0);

            if (tid < DD) {                  // warp 0: vector chain
                int sw = lane & 7;
                // prime ring stages 1..3 (lane copies its own column slice)
                #pragma unroll
                for (int m = 1; m <= 3; ++m) {
                    const float* s = g_E + m * 1024 + lane * 32;
                    unsigned d = smb + (unsigned)(m & 3) * 4096 + lane * 128;
                    #pragma unroll
                    for (int i = 0; i < 8; ++i)
                        cpa16(d + (unsigned)((i ^ sw) << 4), s + i * 4);
                    CP_COMMIT();
                }
                float u = 1.f;
                #pragma unroll
                for (int n = 0; n < 16; ++n) {
                    if (n >= 1) {
                        if (n <= 13)      CP_WAIT(2);
                        else if (n == 14) CP_WAIT(1);
                        else              CP_WAIT(0);
                        __syncwarp();
                    }
                    int m = n + 3;
                    if (m >= 4 && m < 16) {      // refill freed slot
                        const float* s = g_E + m * 1024 + lane * 32;
                        unsigned d = smb + (unsigned)(m & 3) * 4096 + lane * 128;
                        #pragma unroll
                        for (int i = 0; i < 8; ++i)
                            cpa16(d + (unsigned)((i ^ sw) << 4), s + i * 4);
                        CP_COMMIT();
                    }
                    u = chain_step_t(u, sm + (n & 3) * 1024, sU, lane);
                }
                sU[lane] = u;
            }
            __syncthreads();
            // v = u^T Psum (from prefetched registers)
            float a0 = 0.f, a1 = 0.f;
            #pragma unroll
            for (int r = 0; r < DD; ++r) {
                float ur = sU[r];
                a0 = fmaf(ur, pc0[r], a0);
                a1 = fmaf(ur, pc1[r], a1);
            }
            g_v[tid]       = a0;
            g_v[tid + 256] = a1;
            __syncthreads();
            // private release: one flag per consumer block, one writer thread
            if (tid < 128) red_rel_add(&g_flag_v_p[tid], 1);
        }
    } else {
        // ---- Psum[r, half]: blocks 64..127
        int p = blk - 64;
        int r = p >> 1;
        int o = (p & 1) * 256 + tid;
        const float* base = proj + (size_t)r * DD * OUT_DIM + o;
        float acc = 0.f;
        #pragma unroll
        for (int ll = 0; ll < DD; ++ll) acc += base[ll * OUT_DIM];
        g_Psum[r * OUT_DIM + o] = acc;
        __syncthreads();
        if (tid == 0) red_rel_add(&g_cnt_P, 1);
    }

    // ---- epilogue: out[b,o] = s[b]*v[o] + bias[o], 8 rows per block ----------
    float pr = (xa.x * xa.y) * (xa.z * xa.w) * ((xb.x * xb.y) * (xb.z * xb.w));
    #pragma unroll
    for (int off = 16; off; off >>= 1)
        pr *= __shfl_xor_sync(0xffffffffu, pr, off);
    if (lane == 0) sS[w] = pr;

    if (tid == 0) {                       // private flag: single poller
        while (ld_rlx(&g_flag_v_p[blk]) == 0) { }
        (void)ld_acq(&g_flag_v_p[blk]);
        st_relaxed(&g_flag_v_p[blk], 0);  // self-reset for next replay
    }
    __syncthreads();                      // sS ready + v visible

    float4 v = reinterpret_cast<const float4*>(g_v)[o4];
    float4* out4 = reinterpret_cast<float4*>(out);
    int sub = tid >> 7;                   // 0/1
    int b0 = blk * 8;
    #pragma unroll
    for (int i = 0; i < 4; ++i) {
        int row = 2 * i + sub;
        float s = sS[row];
        float4 o;
        o.x = fmaf(s, v.x, bi.x);
        o.y = fmaf(s, v.y, bi.y);
        o.z = fmaf(s, v.z, bi.z);
        o.w = fmaf(s, v.w, bi.w);
        out4[(size_t)(b0 + row) * 128 + o4] = o;
    }
}

// ---------------------------------------------------------------------------
extern "C" void kernel_launch(void* const* d_in, const int* in_sizes, int n_in,
                              void* d_out, int out_size) {
    const float* x     = (const float*)d_in[0];
    const float* cores = (const float*)d_in[1];
    const float* proj  = (const float*)d_in[2];
    const float* bias  = (const float*)d_in[3];
    float* out = (float*)d_out;

    fused_mps<<<128, 256>>>(x, cores, proj, bias, out);
}

// round 9
// speedup vs baseline: 2.2635x; 2.2635x over previous
#include <cuda_runtime.h>

// MPSLayer, fused single kernel (round-7 structure; smem-broadcast chain step).
//   out[b,o]  = s[b]*v[o] + bias[o]
//   s[b]      = prod_n x[b,n]          (local per epilogue block)
//   u         = ones^T @ core_0 @ ... @ core_255
//   Psum[r,o] = sum_l proj[r,l,o]
//   v[o]      = sum_r u[r]*Psum[r,o]
// Tree: 64 blocks ∏4 cores -> D ; blocks 0..15 ∏4 D -> E (row-major) ;
//       block 0: 16-step vector chain via cp.async ring -> u -> v.
// Grid 128 x 256 (blocks 64..127 compute Psum); all co-resident.

#define DD      32
#define N_IN    256
#define BATCH   1024
#define OUT_DIM 512

__device__ __align__(16) float g_D[64 * 1024];
__device__ __align__(16) float g_E[16 * 1024];
__device__ __align__(16) float g_Psum[DD * OUT_DIM];
__device__ __align__(16) float g_v[OUT_DIM];

__device__ int g_cnt_D4[16];     // 4 producers, 1 poller each
__device__ int g_cnt_E;          // 15 producers, 1 poller (block 0)
__device__ int g_cnt_P;          // 64 producers, 1 poller (block 0)
__device__ int g_flag_v_p[128];  // private: 1 writer thread, 1 poller each

// ---- sync primitives --------------------------------------------------------
__device__ __forceinline__ int ld_acq(const int* p) {
    int v;
    asm volatile("ld.acquire.gpu.global.b32 %0, [%1];" : "=r"(v) : "l"(p) : "memory");
    return v;
}
__device__ __forceinline__ int ld_rlx(const int* p) {
    int v;
    asm volatile("ld.relaxed.gpu.global.b32 %0, [%1];" : "=r"(v) : "l"(p) : "memory");
    return v;
}
__device__ __forceinline__ void red_rel_add(int* p, int v) {
    asm volatile("red.release.gpu.global.add.s32 [%0], %1;" :: "l"(p), "r"(v) : "memory");
}
__device__ __forceinline__ void st_relaxed(int* p, int v) {
    asm volatile("st.relaxed.gpu.global.b32 [%0], %1;" :: "l"(p), "r"(v) : "memory");
}
__device__ __forceinline__ void spin_ge(int* cnt, int target) {
    if (threadIdx.x == 0) {
        while (ld_rlx(cnt) < target) { }
        (void)ld_acq(cnt);
    }
    __syncthreads();
}

// ---- cp.async ---------------------------------------------------------------
__device__ __forceinline__ void cpa16(unsigned dst, const float* src) {
    asm volatile("cp.async.ca.shared.global [%0], [%1], 16;" :: "r"(dst), "l"(src));
}
#define CP_COMMIT() asm volatile("cp.async.commit_group;" ::: "memory")
#define CP_WAIT(n)  asm volatile("cp.async.wait_group %0;" :: "n"(n) : "memory")

// ---------------------------------------------------------------------------
// Register-resident 32x32 step: thread owns P[l][4q..4q+3] (l=tid>>3, q=tid&7);
// returns P @ B(smem row-major). Row values gathered by shfl within the 8-lane
// row group.
// ---------------------------------------------------------------------------
__device__ __forceinline__ float4 mm_step_reg(float4 p, const float4* __restrict__ B4,
                                              int lane, int q) {
    float4 acc = make_float4(0.f, 0.f, 0.f, 0.f);
    int grp = lane & 24;
    #pragma unroll
    for (int j = 0; j < 8; ++j) {
        float a; float4 b;
        a = __shfl_sync(0xffffffffu, p.x, grp + j);
        b = B4[(4 * j + 0) * 8 + q];
        acc.x = fmaf(a, b.x, acc.x); acc.y = fmaf(a, b.y, acc.y);
        acc.z = fmaf(a, b.z, acc.z); acc.w = fmaf(a, b.w, acc.w);
        a = __shfl_sync(0xffffffffu, p.y, grp + j);
        b = B4[(4 * j + 1) * 8 + q];
        acc.x = fmaf(a, b.x, acc.x); acc.y = fmaf(a, b.y, acc.y);
        acc.z = fmaf(a, b.z, acc.z); acc.w = fmaf(a, b.w, acc.w);
        a = __shfl_sync(0xffffffffu, p.z, grp + j);
        b = B4[(4 * j + 2) * 8 + q];
        acc.x = fmaf(a, b.x, acc.x); acc.y = fmaf(a, b.y, acc.y);
        acc.z = fmaf(a, b.z, acc.z); acc.w = fmaf(a, b.w, acc.w);
        a = __shfl_sync(0xffffffffu, p.w, grp + j);
        b = B4[(4 * j + 3) * 8 + q];
        acc.x = fmaf(a, b.x, acc.x); acc.y = fmaf(a, b.y, acc.y);
        acc.z = fmaf(a, b.z, acc.z); acc.w = fmaf(a, b.w, acc.w);
    }
    return acc;
}

// Product of 4 consecutive 32x32 matrices (global, row-major), result in regs.
__device__ __forceinline__ float4 mm_chain4_reg(const float4* __restrict__ src4,
                                                float4* sB0, float4* sB1) {
    int tid = threadIdx.x, lane = tid & 31, q = tid & 7;
    float4 p  = src4[tid];
    float4 b1 = src4[256 + tid];
    float4 b2 = src4[512 + tid];
    float4 b3 = src4[768 + tid];
    sB0[tid] = b1; __syncthreads();
    p = mm_step_reg(p, sB0, lane, q);
    sB1[tid] = b2; __syncthreads();
    p = mm_step_reg(p, sB1, lane, q);
    sB0[tid] = b3; __syncthreads();
    p = mm_step_reg(p, sB0, lane, q);
    return p;
}

// ---------------------------------------------------------------------------
// Chain step, smem-broadcast u: lane owns column `lane` of the row-major stage.
// u distributed via 8 broadcast LDS.128 instead of 32 shuffles.
// ---------------------------------------------------------------------------
__device__ __forceinline__ float chain_step_b(float u, const float* __restrict__ stage,
                                              float* __restrict__ sUbuf, int lane) {
    sUbuf[lane] = u;
    __syncwarp();
    const float4* u4 = reinterpret_cast<const float4*>(sUbuf);
    float a0 = 0.f, a1 = 0.f, a2 = 0.f, a3 = 0.f;
    #pragma unroll
    for (int k8 = 0; k8 < 8; ++k8) {
        float4 uu = u4[k8];                       // broadcast (all lanes same addr)
        a0 = fmaf(uu.x, stage[(4 * k8 + 0) * 32 + lane], a0);
        a1 = fmaf(uu.y, stage[(4 * k8 + 1) * 32 + lane], a1);
        a2 = fmaf(uu.z, stage[(4 * k8 + 2) * 32 + lane], a2);
        a3 = fmaf(uu.w, stage[(4 * k8 + 3) * 32 + lane], a3);
    }
    __syncwarp();                                 // reads done before next STS
    return (a0 + a1) + (a2 + a3);
}

// ---------------------------------------------------------------------------
__global__ void __launch_bounds__(256) fused_mps(
    const float* __restrict__ x, const float* __restrict__ cores,
    const float* __restrict__ proj, const float* __restrict__ bias,
    float* __restrict__ out) {

    __shared__ __align__(16) float sm[4 * 1024];   // 4 ring stages x 4KB
    __shared__ __align__(16) float sU[DD];
    __shared__ float sS[8];
    int tid = threadIdx.x;
    int blk = blockIdx.x;
    int lane = tid & 31;
    int w = tid >> 5;

    // ---- entry prefetches ----------------------------------------------------
    int o4 = tid & 127;
    float4 bi = reinterpret_cast<const float4*>(bias)[o4];
    const float4* x4 = reinterpret_cast<const float4*>(x);
    int xrow = blk * 8 + w;
    float4 xa = x4[xrow * 64 + lane];
    float4 xb = x4[xrow * 64 + 32 + lane];

    float4* stg0 = reinterpret_cast<float4*>(sm);
    float4* stg1 = reinterpret_cast<float4*>(sm + 1024);
    unsigned smb = (unsigned)__cvta_generic_to_shared(sm);

    if (blk < 64) {
        // ---- level 1: D[blk] = product of 4 cores
        float4 p = mm_chain4_reg(
            reinterpret_cast<const float4*>(cores) + (size_t)blk * 1024, stg0, stg1);
        reinterpret_cast<float4*>(g_D)[blk * 256 + tid] = p;
        __syncthreads();
        if (tid == 0) red_rel_add(&g_cnt_D4[blk >> 2], 1);

        if (blk < 16) {
            // ---- level 2: E[blk] = D[4blk] @ .. @ D[4blk+3]
            spin_ge(&g_cnt_D4[blk], 4);
            if (tid == 0) st_relaxed(&g_cnt_D4[blk], 0);
            float4 e = mm_chain4_reg(
                reinterpret_cast<const float4*>(g_D) + (size_t)blk * 1024, stg0, stg1);
            if (blk > 0) {
                reinterpret_cast<float4*>(g_E)[blk * 256 + tid] = e;   // coalesced
                __syncthreads();
                if (tid == 0) red_rel_add(&g_cnt_E, 1);
            } else {
                __syncthreads();           // mm reads of stage 0 complete
                stg0[tid] = e;             // E0 straight into ring stage 0
            }
        }
        if (blk == 0) {
            // Psum ready early: sync + prefetch its columns into registers
            spin_ge(&g_cnt_P, 64);
            if (tid == 0) st_relaxed(&g_cnt_P, 0);
            float pc0[DD], pc1[DD];
            #pragma unroll
            for (int r = 0; r < DD; ++r) pc0[r] = g_Psum[r * OUT_DIM + tid];
            #pragma unroll
            for (int r = 0; r < DD; ++r) pc1[r] = g_Psum[r * OUT_DIM + tid + 256];

            spin_ge(&g_cnt_E, 15);
            if (tid == 0) st_relaxed(&g_cnt_E, 0);

            if (tid < DD) {                 // warp 0: vector chain
                // prime ring stages 1..3
                #pragma unroll
                for (int m = 1; m <= 3; ++m) {
                    const float* s = g_E + m * 1024 + lane * 4;
                    unsigned d = smb + (unsigned)(m & 3) * 4096 + lane * 16;
                    #pragma unroll
                    for (int i = 0; i < 8; ++i) cpa16(d + i * 512, s + i * 128);
                    CP_COMMIT();
                }
                float u = 1.f;
                #pragma unroll
                for (int n = 0; n < 16; ++n) {
                    if (n >= 1) {
                        if (n <= 13)      CP_WAIT(2);
                        else if (n == 14) CP_WAIT(1);
                        else              CP_WAIT(0);
                        __syncwarp();
                    }
                    int m = n + 3;
                    if (m >= 4 && m < 16) {     // refill freed slot
                        const float* s = g_E + m * 1024 + lane * 4;
                        unsigned d = smb + (unsigned)(m & 3) * 4096 + lane * 16;
                        #pragma unroll
                        for (int i = 0; i < 8; ++i) cpa16(d + i * 512, s + i * 128);
                        CP_COMMIT();
                    }
                    u = chain_step_b(u, sm + (n & 3) * 1024, sU, lane);
                }
                sU[lane] = u;
            }
            __syncthreads();
            // v = u^T Psum (from prefetched registers)
            float a0 = 0.f, a1 = 0.f;
            #pragma unroll
            for (int r = 0; r < DD; ++r) {
                float ur = sU[r];
                a0 = fmaf(ur, pc0[r], a0);
                a1 = fmaf(ur, pc1[r], a1);
            }
            g_v[tid]       = a0;
            g_v[tid + 256] = a1;
            __syncthreads();
            // private release: one flag per consumer block, one writer thread
            if (tid < 128) red_rel_add(&g_flag_v_p[tid], 1);
        }
    } else {
        // ---- Psum[r, half]: blocks 64..127
        int p = blk - 64;
        int r = p >> 1;
        int o = (p & 1) * 256 + tid;
        const float* base = proj + (size_t)r * DD * OUT_DIM + o;
        float acc = 0.f;
        #pragma unroll
        for (int ll = 0; ll < DD; ++ll) acc += base[ll * OUT_DIM];
        g_Psum[r * OUT_DIM + o] = acc;
        __syncthreads();
        if (tid == 0) red_rel_add(&g_cnt_P, 1);
    }

    // ---- epilogue: out[b,o] = s[b]*v[o] + bias[o], 8 rows per block ----------
    float pr = (xa.x * xa.y) * (xa.z * xa.w) * ((xb.x * xb.y) * (xb.z * xb.w));
    #pragma unroll
    for (int off = 16; off; off >>= 1)
        pr *= __shfl_xor_sync(0xffffffffu, pr, off);
    if (lane == 0) sS[w] = pr;

    if (tid == 0) {                       // private flag: single poller
        while (ld_rlx(&g_flag_v_p[blk]) == 0) { }
        (void)ld_acq(&g_flag_v_p[blk]);
        st_relaxed(&g_flag_v_p[blk], 0);  // self-reset for next replay
    }
    __syncthreads();                      // sS ready + v visible

    float4 v = reinterpret_cast<const float4*>(g_v)[o4];
    float4* out4 = reinterpret_cast<float4*>(out);
    int sub = tid >> 7;                   // 0/1
    int b0 = blk * 8;
    #pragma unroll
    for (int i = 0; i < 4; ++i) {
        int row = 2 * i + sub;
        float s = sS[row];
        float4 o;
        o.x = fmaf(s, v.x, bi.x);
        o.y = fmaf(s, v.y, bi.y);
        o.z = fmaf(s, v.z, bi.z);
        o.w = fmaf(s, v.w, bi.w);
        out4[(size_t)(b0 + row) * 128 + o4] = o;
    }
}

// ---------------------------------------------------------------------------
extern "C" void kernel_launch(void* const* d_in, const int* in_sizes, int n_in,
                              void* d_out, int out_size) {
    const float* x     = (const float*)d_in[0];
    const float* cores = (const float*)d_in[1];
    const float* proj  = (const float*)d_in[2];
    const float* bias  = (const float*)d_in[3];
    float* out = (float*)d_out;

    fused_mps<<<128, 256>>>(x, cores, proj, bias, out);
}